// round 17
// baseline (speedup 1.0000x reference)
#include <cuda_runtime.h>
#include <cuda_bf16.h>
#include <cstdint>

// Conv2d: x[3,2048,2048] fp32 * k[16,3,3,3] fp32, pad=1, stride=1 -> out[16,2048,2048]
//
// R17 (v12): v11 (bf16 m16n8k16, K=32 slot map, smem weight table, PRMT staging)
// with a block-interleaved slot layout:
//   storage position fr(c) = (c&~15) | ((c&7)<<1) | ((c>>3)&1)
//   -> slots (16g+lr, 16g+lr+8) are ADJACENT u64s = one aligned LDS.128 (uint4)
//   -> main loop: 4 LDS.128 per 16-px group (was 8 LDS.64), offsets fold to
//      immediates in the unrolled loop. Bank classes {0,4,8,12}+4*wid preserved;
//      per-phase 16B chunks distinct mod 8 -> conflict-free.
//   zero-weight K-slot rebased to warp*MRS (finite data, completes class set).

#define HW    2048
#define PLANE (2048 * 2048)

// u64-slot layout (u64 units)
#define MPL   1324
#define MRS   132
#define PBASE 3972
#define SBASE 5300
#define WBASE 6616          // weight table: 16 slots x 16 oc
#define NU64  6872
#define SMEM_BYTES (NU64 * 8)

typedef unsigned long long u64;

__device__ __forceinline__ int fr(int c) {
    return (c & ~15) | ((c & 7) << 1) | ((c >> 3) & 1);
}

__device__ __forceinline__ void mma16(float* c, const unsigned* a,
                                      unsigned b0, unsigned b1) {
    asm volatile(
        "mma.sync.aligned.m16n8k16.row.col.f32.bf16.bf16.f32 "
        "{%0,%1,%2,%3}, {%4,%5,%6,%7}, {%8,%9}, {%0,%1,%2,%3};"
        : "+f"(c[0]), "+f"(c[1]), "+f"(c[2]), "+f"(c[3])
        : "r"(a[0]), "r"(a[1]), "r"(a[2]), "r"(a[3]), "r"(b0), "r"(b1));
}

__device__ __forceinline__ unsigned prmt(unsigned a, unsigned b, unsigned sel) {
    unsigned r;
    asm("prmt.b32 %0, %1, %2, %3;" : "=r"(r) : "r"(a), "r"(b), "r"(sel));
    return r;
}

// (bf16(hi_val) << 16) | bf16(lo_val)
__device__ __forceinline__ unsigned bf16x2(float hi_val, float lo_val) {
    unsigned r;
    asm("cvt.rn.bf16x2.f32 %0, %1, %2;" : "=r"(r) : "f"(hi_val), "f"(lo_val));
    return r;
}

// Weight pair for K-slot p, oc -> (bh = bf16x2 hi parts, bl = lo parts).
__device__ __forceinline__ void wpair(const float* kern, int p, int oc,
                                      unsigned& bh, unsigned& bl) {
    float wa = 0.0f, wb = 0.0f;
    if (p < 9) {
        int ic = p / 3, kh = p - 3 * ic;
        const float* kp = kern + oc * 27 + ic * 9 + kh * 3;
        wa = kp[0]; wb = kp[1];
    } else if (p < 12) {
        int kh = p - 9;
        wa = kern[oc * 27 + 0 + kh * 3 + 2];
        wb = kern[oc * 27 + 9 + kh * 3 + 2];
    } else if (p < 15) {
        int kh = p - 12;
        wa = kern[oc * 27 + 18 + kh * 3 + 2];
    }
    __nv_bfloat16 wah = __float2bfloat16(wa);
    __nv_bfloat16 wbh = __float2bfloat16(wb);
    float ra = wa - __bfloat162float(wah);
    float rb = wb - __bfloat162float(wbh);
    bh = (unsigned)__bfloat16_as_ushort(wah)
       | ((unsigned)__bfloat16_as_ushort(wbh) << 16);
    bl = bf16x2(rb, ra);
}

__global__ __launch_bounds__(256, 4)
void conv3x3_bf16_v12_kernel(const float* __restrict__ x,
                             const float* __restrict__ kern,
                             float* __restrict__ out) {
    extern __shared__ u64 S64[];
    uint2* S2 = reinterpret_cast<uint2*>(S64);
    uint4* S4 = reinterpret_cast<uint4*>(S64);

    const int tid  = threadIdx.x;
    const int bx   = blockIdx.x;            // 16 tiles of 128 cols
    const int by   = blockIdx.y;            // 256 tiles of 8 rows
    const int row0 = by * 8 - 1;
    const int col0 = bx * 128 - 1;
    const int warp = tid >> 5;              // 8 warps; warp = output row in tile
    const int lane = tid & 31;
    const int lq   = lane & 3;
    const int lr   = lane >> 2;

    // ---- Stage weight table: 16 slots x 16 oc, one entry per thread ----
    {
        int p  = tid >> 4;
        int oc = tid & 15;
        unsigned bh, bl;
        wpair(kern, p, oc, bh, bl);
        S2[WBASE + tid] = make_uint2(bh, bl);
    }

    // ---- Stage input tile: 40 (row, seg32) units + 20-unit tail ----
    #pragma unroll
    for (int i = 0; i < 5; ++i) {
        int u = warp + 8 * i;               // 0..39
        int r = u >> 2;                     // 0..9
        int c = ((u & 3) << 5) + lane;      // 0..127
        int gy = row0 + r;
        int gx = col0 + c;
        bool rok = (unsigned)gy < (unsigned)HW;
        const float* base = x + gy * HW;

        unsigned ua[3], ub[3];
        float la[3], lb[3];
        #pragma unroll
        for (int ic = 0; ic < 3; ++ic) {
            float va = (rok && (unsigned)gx < (unsigned)HW)
                       ? base[ic * PLANE + gx] : 0.0f;
            float vb = (rok && (unsigned)(gx + 1) < (unsigned)HW)
                       ? base[ic * PLANE + gx + 1] : 0.0f;
            ua[ic] = __float_as_uint(va);
            ub[ic] = __float_as_uint(vb);
            la[ic] = va - __uint_as_float(ua[ic] & 0xFFFF0000u);
            lb[ic] = vb - __uint_as_float(ub[ic] & 0xFFFF0000u);
        }

        int fc  = fr(c);
        #pragma unroll
        for (int ic = 0; ic < 3; ++ic) {
            unsigned hp = prmt(ua[ic], ub[ic], 0x7632);
            unsigned lp = bf16x2(lb[ic], la[ic]);
            S2[ic * MPL + r * MRS + fc] = make_uint2(hp, lp);
        }
        if (c >= 2) {
            int fq = fr(c - 2);
            unsigned hp = prmt(ua[0], ua[1], 0x7632);
            unsigned lp = bf16x2(la[1], la[0]);
            S2[PBASE + r * MRS + fq] = make_uint2(hp, lp);
            unsigned hs = ua[2] >> 16;
            unsigned ls = bf16x2(0.0f, la[2]);
            S2[SBASE + r * MRS + fq] = make_uint2(hs, ls);
        }
    }
    // tail: c = 128, 129 -> P slots 126,127 and S slots 126,127
    if (tid < 20) {
        int r = tid >> 1;
        int c = 128 + (tid & 1);
        int gy = row0 + r;
        int gx = col0 + c;
        bool ok = (unsigned)gy < (unsigned)HW && (unsigned)gx < (unsigned)HW;
        float v0 = ok ? x[0 * PLANE + gy * HW + gx] : 0.0f;
        float v1 = ok ? x[1 * PLANE + gy * HW + gx] : 0.0f;
        float v2 = ok ? x[2 * PLANE + gy * HW + gx] : 0.0f;
        unsigned u0 = __float_as_uint(v0), u1 = __float_as_uint(v1),
                 u2 = __float_as_uint(v2);
        float l0 = v0 - __uint_as_float(u0 & 0xFFFF0000u);
        float l1 = v1 - __uint_as_float(u1 & 0xFFFF0000u);
        float l2 = v2 - __uint_as_float(u2 & 0xFFFF0000u);
        int fq = fr(c - 2);
        S2[PBASE + r * MRS + fq] =
            make_uint2(prmt(u0, u1, 0x7632), bf16x2(l1, l0));
        S2[SBASE + r * MRS + fq] =
            make_uint2(u2 >> 16, bf16x2(0.0f, l2));
    }

    __syncthreads();

    // ---- B fragments from the smem weight table (8 LDS.64) ----
    unsigned Wh[2][2][2], Wl[2][2][2];
    #pragma unroll
    for (int ch = 0; ch < 2; ++ch)
        #pragma unroll
        for (int h = 0; h < 2; ++h) {
            uint2 w0 = S2[WBASE + (8 * ch + lq) * 16 + 8 * h + lr];
            uint2 w1 = S2[WBASE + (8 * ch + 4 + lq) * 16 + 8 * h + lr];
            Wh[ch][h][0] = w0.x; Wl[ch][h][0] = w0.y;
            Wh[ch][h][1] = w1.x; Wl[ch][h][1] = w1.y;
        }

    // ---- A slot-row bases (u64, even) -> uint4 indices J = base/2 + lr ----
    auto rowbase = [&](int p) -> int {
        if (p < 9)  return (p / 3) * MPL + (warp + p % 3) * MRS;
        if (p < 12) return PBASE + (warp + (p - 9)) * MRS;
        if (p < 15) return SBASE + (warp + (p - 12)) * MRS;
        return warp * MRS;                  // zero-weight slot: finite, class 4*warp
    };
    const int J00 = rowbase(lq) / 2 + lr;
    const int J01 = rowbase(4 + lq) / 2 + lr;
    const int J10 = rowbase(8 + lq) / 2 + lr;
    const int J11 = rowbase(12 + lq) / 2 + lr;

    const int Ybase = (by * 8 + warp) * HW;

    // ---- 8 groups of 16 pixels: 4 LDS.128 + 12 MMA each ----
    #pragma unroll
    for (int g = 0; g < 8; ++g) {
        float cA[2][4], cB[2][4];
        #pragma unroll
        for (int h = 0; h < 2; ++h)
            #pragma unroll
            for (int i = 0; i < 4; ++i) { cA[h][i] = 0.0f; cB[h][i] = 0.0f; }

        // Q = {ah[j], al[j], ah[j+1], al[j+1]} for slot pair (16g+lr, 16g+lr+8)
        uint4 Q0 = S4[J00 + 8 * g];
        uint4 Q1 = S4[J01 + 8 * g];
        uint4 Q2 = S4[J10 + 8 * g];
        uint4 Q3 = S4[J11 + 8 * g];

        {   // chunk 0
            unsigned ah[4] = {Q0.x, Q0.z, Q1.x, Q1.z};
            unsigned al[4] = {Q0.y, Q0.w, Q1.y, Q1.w};
            #pragma unroll
            for (int h = 0; h < 2; ++h) {
                mma16(cA[h], ah, Wh[0][h][0], Wh[0][h][1]);
                mma16(cB[h], ah, Wl[0][h][0], Wl[0][h][1]);
                mma16(cB[h], al, Wh[0][h][0], Wh[0][h][1]);
            }
        }
        {   // chunk 1
            unsigned ah[4] = {Q2.x, Q2.z, Q3.x, Q3.z};
            unsigned al[4] = {Q2.y, Q2.w, Q3.y, Q3.w};
            #pragma unroll
            for (int h = 0; h < 2; ++h) {
                mma16(cA[h], ah, Wh[1][h][0], Wh[1][h][1]);
                mma16(cB[h], ah, Wl[1][h][0], Wl[1][h][1]);
                mma16(cB[h], al, Wh[1][h][0], Wh[1][h][1]);
            }
        }

        // ---- Store: c0:(lr, oc 2lq) c1:(lr, 2lq+1) c2:(lr+8, 2lq) c3:(lr+8, 2lq+1)
        const int X = bx * 128 + g * 16 + lr;
        #pragma unroll
        for (int h = 0; h < 2; ++h) {
            float* p = out + (8 * h + 2 * lq) * PLANE + Ybase + X;
            p[0]         = cA[h][0] + cB[h][0];
            p[PLANE]     = cA[h][1] + cB[h][1];
            p[8]         = cA[h][2] + cB[h][2];
            p[PLANE + 8] = cA[h][3] + cB[h][3];
        }
    }
}

extern "C" void kernel_launch(void* const* d_in, const int* in_sizes, int n_in,
                              void* d_out, int out_size) {
    const float* x = (const float*)d_in[0];   // [3, 2048, 2048]
    const float* k = (const float*)d_in[1];   // [16, 3, 3, 3]
    float* out     = (float*)d_out;           // [16, 2048, 2048]

    cudaFuncSetAttribute(conv3x3_bf16_v12_kernel,
                         cudaFuncAttributeMaxDynamicSharedMemorySize, SMEM_BYTES);
    dim3 grid(HW / 128, HW / 8);              // (16, 256)
    conv3x3_bf16_v12_kernel<<<grid, 256, SMEM_BYTES>>>(x, k, out);
}